// round 1
// baseline (speedup 1.0000x reference)
#include <cuda_runtime.h>

// Problem constants
//   X, Y: [64, 1, 512, 512] float32
//   3x3 separable window, SAME conv, crop [5:-5, 5:-5] -> [64, 502, 502]
//   loss = sum_b mean_hw( sxx*syy - 2*sxy )

#define FULLMASK 0xFFFFFFFFu

__device__ double g_acc;

// sqrt-factored separable window coefficients (w = outer(a_vec, a_vec))
// a^2 = 0.09474166, b^2 = 0.14776132, a*b = 0.11831801
#define WA 0.30780134f
#define WB 0.38439735f

struct H5 { float x[4], y[4], xx[4], yy[4], xy[4]; };

__device__ __forceinline__ void hrow(const float* __restrict__ Xr,
                                     const float* __restrict__ Yr,
                                     int ib, int hb, int lane, H5& h) {
    // lane owns input cols [ib, ib+3]; needs ib..ib+5 for 4 horizontal outputs
    float4 xv = *(const float4*)(Xr + ib);
    float4 yv = *(const float4*)(Yr + ib);
    float rx0 = __shfl_down_sync(FULLMASK, xv.x, 1);
    float rx1 = __shfl_down_sync(FULLMASK, xv.y, 1);
    float ry0 = __shfl_down_sync(FULLMASK, yv.x, 1);
    float ry1 = __shfl_down_sync(FULLMASK, yv.y, 1);
    if (lane == 31) {   // right halo for the last lane comes from an extra load
        float2 ex = *(const float2*)(Xr + hb);
        float2 ey = *(const float2*)(Yr + hb);
        rx0 = ex.x; rx1 = ex.y; ry0 = ey.x; ry1 = ey.y;
    }
    float xs[6] = {xv.x, xv.y, xv.z, xv.w, rx0, rx1};
    float ys[6] = {yv.x, yv.y, yv.z, yv.w, ry0, ry1};
#pragma unroll
    for (int k = 0; k < 4; k++) {
        h.x[k]  = WA * (xs[k] + xs[k + 2])                     + WB * xs[k + 1];
        h.y[k]  = WA * (ys[k] + ys[k + 2])                     + WB * ys[k + 1];
        h.xx[k] = WA * (xs[k]*xs[k] + xs[k + 2]*xs[k + 2])     + WB * (xs[k + 1]*xs[k + 1]);
        h.yy[k] = WA * (ys[k]*ys[k] + ys[k + 2]*ys[k + 2])     + WB * (ys[k + 1]*ys[k + 1]);
        h.xy[k] = WA * (xs[k]*ys[k] + xs[k + 2]*ys[k + 2])     + WB * (xs[k + 1]*ys[k + 1]);
    }
}

__global__ void __launch_bounds__(128) zero_kernel() { g_acc = 0.0; }

__global__ void __launch_bounds__(128)
loss_kernel(const float* __restrict__ X, const float* __restrict__ Y) {
    const int lane = threadIdx.x & 31;
    // 4096 warp work-units: unit = b*64 + s*16 + t
    const int unit = blockIdx.x * 4 + (threadIdx.x >> 5);
    const int b = unit >> 6;
    const int s = (unit >> 4) & 3;   // column stripe 0..3 (128 output cols each)
    const int t = unit & 15;         // row strip 0..15 (32 output rows each)

    const int cb   = 5 + 128 * s;            // first output col of stripe
    const int r0   = 5 + 32 * t;             // first output row of strip
    const int rend = min(r0 + 32, 507);      // exclusive

    const int j0 = cb + 4 * lane;            // first output col this lane owns
    const int ib = min(j0 - 1, 508);         // float4 input base (4-aligned; clamp keeps in-row)
    const int hb = min(j0 + 3, 510);         // lane-31 halo float2 base (even; clamp keeps in-row)

    const float* Xb = X + ((size_t)b << 18); // 512*512
    const float* Yb = Y + ((size_t)b << 18);

    float mk[4];
#pragma unroll
    for (int k = 0; k < 4; k++) mk[k] = (j0 + k < 507) ? 1.0f : 0.0f;

    H5 h;
    float Vpx[4], Vpy[4], Vpxx[4], Vpyy[4], Vpxy[4];
    float Vqx[4], Vqy[4], Vqxx[4], Vqyy[4], Vqxy[4];

    // Prime: input row r0-1 seeds Vq (coeff a for output row r0)
    hrow(Xb + (size_t)(r0 - 1) * 512, Yb + (size_t)(r0 - 1) * 512, ib, hb, lane, h);
#pragma unroll
    for (int k = 0; k < 4; k++) {
        Vqx[k]  = WA * h.x[k];   Vqy[k]  = WA * h.y[k];
        Vqxx[k] = WA * h.xx[k];  Vqyy[k] = WA * h.yy[k];  Vqxy[k] = WA * h.xy[k];
    }
    // Prime: input row r0 -> Vp = a*H[r0-1] + b*H[r0] (for output r0); Vq = a*H[r0]
    hrow(Xb + (size_t)r0 * 512, Yb + (size_t)r0 * 512, ib, hb, lane, h);
#pragma unroll
    for (int k = 0; k < 4; k++) {
        Vpx[k]  = Vqx[k]  + WB * h.x[k];   Vqx[k]  = WA * h.x[k];
        Vpy[k]  = Vqy[k]  + WB * h.y[k];   Vqy[k]  = WA * h.y[k];
        Vpxx[k] = Vqxx[k] + WB * h.xx[k];  Vqxx[k] = WA * h.xx[k];
        Vpyy[k] = Vqyy[k] + WB * h.yy[k];  Vqyy[k] = WA * h.yy[k];
        Vpxy[k] = Vqxy[k] + WB * h.xy[k];  Vqxy[k] = WA * h.xy[k];
    }

    float acc = 0.0f;
#pragma unroll 4
    for (int i = r0 + 1; i <= rend; ++i) {
        hrow(Xb + (size_t)i * 512, Yb + (size_t)i * 512, ib, hb, lane, h);
#pragma unroll
        for (int k = 0; k < 4; k++) {
            // finish output row i-1
            float vx  = Vpx[k]  + WA * h.x[k];
            float vy  = Vpy[k]  + WA * h.y[k];
            float vxx = Vpxx[k] + WA * h.xx[k];
            float vyy = Vpyy[k] + WA * h.yy[k];
            float vxy = Vpxy[k] + WA * h.xy[k];
            float sxx = vxx - vx * vx;
            float syy = vyy - vy * vy;
            float sxy = vxy - vx * vy;
            acc = fmaf(mk[k], fmaf(sxx, syy, -2.0f * sxy), acc);
            // roll accumulators
            Vpx[k]  = Vqx[k]  + WB * h.x[k];   Vqx[k]  = WA * h.x[k];
            Vpy[k]  = Vqy[k]  + WB * h.y[k];   Vqy[k]  = WA * h.y[k];
            Vpxx[k] = Vqxx[k] + WB * h.xx[k];  Vqxx[k] = WA * h.xx[k];
            Vpyy[k] = Vqyy[k] + WB * h.yy[k];  Vqyy[k] = WA * h.yy[k];
            Vpxy[k] = Vqxy[k] + WB * h.xy[k];  Vqxy[k] = WA * h.xy[k];
        }
    }

    // warp reduction, one double atomic per warp
#pragma unroll
    for (int o = 16; o > 0; o >>= 1) acc += __shfl_xor_sync(FULLMASK, acc, o);
    if (lane == 0) atomicAdd(&g_acc, (double)acc);
}

__global__ void __launch_bounds__(128) finalize_kernel(float* __restrict__ out) {
    // per-sample mean over 502*502, summed over batch
    out[0] = (float)(g_acc * (1.0 / 252004.0));
}

extern "C" void kernel_launch(void* const* d_in, const int* in_sizes, int n_in,
                              void* d_out, int out_size) {
    const float* X = (const float*)d_in[0];
    const float* Y = (const float*)d_in[1];
    float* out = (float*)d_out;

    zero_kernel<<<1, 128>>>();
    // 4096 warps = 64 images * 4 col-stripes * 16 row-strips; 4 warps/block
    loss_kernel<<<1024, 128>>>(X, Y);
    finalize_kernel<<<1, 128>>>(out);
}